// round 1
// baseline (speedup 1.0000x reference)
#include <cuda_runtime.h>
#include <cstddef>

// PerLeadTimeLSTM: B=131072, LEADS=42, INPUT_DIM=2, HIDDEN=10
// Single timestep, zero init state => f gate unused.
// gates[b,t,r] = W_ih[t,r,:] . x[b,t,:] + b_ih[t,r] + b_hh[t,r]
// c = sigmoid(i)*tanh(g); h = sigmoid(o)*tanh(c)
// y[b,t,d] = W_fc[t,d,:] . h + b_fc[t,d]

#define TPB 128
#define NT 42
#define NH 10
// Per-lead packed weights: 116 floats (16B-aligned stride)
//  [0..59]   W_ih rows for i,g,o: [r*2+d], r in 0..29 (i:0-9, g:10-19, o:20-29)
//  [60..89]  bias (b_ih+b_hh) for same 30 rows
//  [90..109] W_fc [d*10+h]
//  [110.111] b_fc
//  [112.115] pad
#define WSTRIDE 116

__device__ __forceinline__ float ex2f(float x) {
    float r; asm("ex2.approx.f32 %0, %1;" : "=f"(r) : "f"(x)); return r;
}
__device__ __forceinline__ float rcpf(float x) {
    float r; asm("rcp.approx.f32 %0, %1;" : "=f"(r) : "f"(x)); return r;
}

__global__ void __launch_bounds__(TPB)
lstm42_kernel(const float* __restrict__ x,
              const float* __restrict__ Wih,
              const float* __restrict__ bih,
              const float* __restrict__ bhh,
              const float* __restrict__ Wfc,
              const float* __restrict__ bfc,
              float* __restrict__ y)
{
    __shared__ __align__(16) float sw[NT * WSTRIDE];

    const int tid = threadIdx.x;

    // Cooperative pack of weights into shared memory.
    for (int idx = tid; idx < NT * WSTRIDE; idx += TPB) {
        int t = idx / WSTRIDE;
        int k = idx - t * WSTRIDE;
        float v = 0.f;
        if (k < 60) {
            int r = k >> 1, d = k & 1;
            int row = (r < 10) ? r : r + 10;     // skip f rows 10..19
            v = Wih[t * 80 + row * 2 + d];
        } else if (k < 90) {
            int r = k - 60;
            int row = (r < 10) ? r : r + 10;
            v = bih[t * 40 + row] + bhh[t * 40 + row];
        } else if (k < 110) {
            v = Wfc[t * 20 + (k - 90)];
        } else if (k < 112) {
            v = bfc[t * 2 + (k - 110)];
        }
        sw[idx] = v;
    }
    __syncthreads();

    const int b = blockIdx.x * TPB + tid;   // grid sized so b < 131072 exactly

    // Load this batch row's 42*(x0,x1) = 84 contiguous floats into registers.
    float v[84];
    const float4* xp = reinterpret_cast<const float4*>(x + (size_t)b * 84);
    float4* vp = reinterpret_cast<float4*>(v);
#pragma unroll
    for (int i = 0; i < 21; i++) vp[i] = xp[i];

    const float NL2E  = -1.4426950408889634f;   // -log2(e)
    const float N2L2E = -2.8853900817779268f;   // -2*log2(e)

#pragma unroll
    for (int t = 0; t < NT; t++) {
        const float* w = &sw[t * WSTRIDE];
        float x0 = v[2 * t];
        float x1 = v[2 * t + 1];
        float y0 = w[110];
        float y1 = w[111];
#pragma unroll
        for (int h = 0; h < NH; h++) {
            float gi = fmaf(w[2*h],      x0, fmaf(w[2*h+1],      x1, w[60 + h]));
            float gg = fmaf(w[20 + 2*h], x0, fmaf(w[21 + 2*h],   x1, w[70 + h]));
            float go = fmaf(w[40 + 2*h], x0, fmaf(w[41 + 2*h],   x1, w[80 + h]));

            // c = sigmoid(gi) * tanh(gg)
            //   = (1 - e^{-2gg}) / ((1 + e^{-gi}) * (1 + e^{-2gg}))   [one rcp]
            float ti = ex2f(NL2E  * gi);
            float tg = ex2f(N2L2E * gg);
            float c  = (1.f - tg) * rcpf((1.f + ti) * (1.f + tg));

            // hh = sigmoid(go) * tanh(c), same fusion
            float to = ex2f(NL2E  * go);
            float tc = ex2f(N2L2E * c);
            float hh = (1.f - tc) * rcpf((1.f + to) * (1.f + tc));

            y0 = fmaf(w[90 + h],  hh, y0);
            y1 = fmaf(w[100 + h], hh, y1);
        }
        v[2 * t]     = y0;
        v[2 * t + 1] = y1;
    }

    float4* yp = reinterpret_cast<float4*>(y + (size_t)b * 84);
#pragma unroll
    for (int i = 0; i < 21; i++) yp[i] = vp[i];
}

extern "C" void kernel_launch(void* const* d_in, const int* in_sizes, int n_in,
                              void* d_out, int out_size)
{
    const float* x   = (const float*)d_in[0];
    const float* Wih = (const float*)d_in[1];
    const float* bih = (const float*)d_in[2];
    const float* bhh = (const float*)d_in[3];
    const float* Wfc = (const float*)d_in[4];
    const float* bfc = (const float*)d_in[5];
    float* y = (float*)d_out;

    const int B = 131072;
    lstm42_kernel<<<B / TPB, TPB>>>(x, Wih, bih, bhh, Wfc, bfc, y);
}

// round 4
// speedup vs baseline: 1.1243x; 1.1243x over previous
#include <cuda_runtime.h>
#include <cstddef>

// PerLeadTimeLSTM: B=131072, LEADS=42, INPUT_DIM=2, HIDDEN=10
// Single timestep, zero init state => f gate dead.
// Split each batch row across PARTS=6 threads (7 leads each) for occupancy;
// x offset for thread m is m*14 floats -> perfectly coalesced.

#define TPB 256
#define NT 42
#define NH 10
#define PARTS 6
#define LPT 7            // leads per thread
#define FPT (2 * LPT)    // floats per thread (14)

// Per-(lead,h) packed weights: 12 floats = 3 float4
//  A: [wi0, wi1, wg0, wg1]
//  B: [wo0, wo1, bias_i, bias_g]
//  C: [bias_o, wfc_d0, wfc_d1, pad]
#define HSTRIDE 12
#define TSTRIDE (NH * HSTRIDE)   // 120 floats per lead

__device__ __forceinline__ float tanh_a(float v) {
    float r; asm("tanh.approx.f32 %0, %1;" : "=f"(r) : "f"(v)); return r;
}

__global__ void __launch_bounds__(TPB)
lstm42_kernel(const float* __restrict__ x,
              const float* __restrict__ Wih,
              const float* __restrict__ bih,
              const float* __restrict__ bhh,
              const float* __restrict__ Wfc,
              const float* __restrict__ bfc,
              float* __restrict__ y)
{
    __shared__ __align__(16) float sw[NT * TSTRIDE];
    __shared__ float sfc[NT * 2];

    const int tid = threadIdx.x;

    // Cooperative pack of weights into shared memory.
    for (int idx = tid; idx < NT * TSTRIDE; idx += TPB) {
        int t = idx / TSTRIDE;
        int r = idx - t * TSTRIDE;
        int h = r / HSTRIDE;
        int k = r - h * HSTRIDE;
        float v = 0.f;
        // PyTorch gate row order: i=0..9, f=10..19, g=20..29, o=30..39
        if (k < 2)       v = Wih[t * 80 + h * 2 + k];                 // i
        else if (k < 4)  v = Wih[t * 80 + (20 + h) * 2 + (k - 2)];    // g
        else if (k < 6)  v = Wih[t * 80 + (30 + h) * 2 + (k - 4)];    // o
        else if (k == 6) v = bih[t * 40 + h]      + bhh[t * 40 + h];
        else if (k == 7) v = bih[t * 40 + 20 + h] + bhh[t * 40 + 20 + h];
        else if (k == 8) v = bih[t * 40 + 30 + h] + bhh[t * 40 + 30 + h];
        else if (k == 9)  v = Wfc[t * 20 + h];         // d=0 row
        else if (k == 10) v = Wfc[t * 20 + 10 + h];    // d=1 row
        sw[idx] = v;
    }
    for (int idx = tid; idx < NT * 2; idx += TPB) sfc[idx] = bfc[idx];
    __syncthreads();

    const unsigned mw = blockIdx.x * TPB + tid;
    const int part = (int)(mw % PARTS);
    const size_t m = (size_t)mw;

    // Load this thread's 14 contiguous floats (7 leads x 2).
    float v[FPT];
    const float2* xp = reinterpret_cast<const float2*>(x + m * FPT);
    float2* vp = reinterpret_cast<float2*>(v);
#pragma unroll
    for (int i = 0; i < LPT; i++) vp[i] = xp[i];

#pragma unroll 1
    for (int lt = 0; lt < LPT; lt++) {
        const int t = part * LPT + lt;
        const float x0 = v[2 * lt];
        const float x1 = v[2 * lt + 1];
        float y0 = sfc[2 * t];
        float y1 = sfc[2 * t + 1];
        const float4* w4 = reinterpret_cast<const float4*>(sw + t * TSTRIDE);
#pragma unroll
        for (int h = 0; h < NH; h++) {
            float4 A = w4[h * 3 + 0];
            float4 B = w4[h * 3 + 1];
            float4 C = w4[h * 3 + 2];
            float gi = fmaf(A.x, x0, fmaf(A.y, x1, B.z));
            float gg = fmaf(A.z, x0, fmaf(A.w, x1, B.w));
            float go = fmaf(B.x, x0, fmaf(B.y, x1, C.x));

            float si = fmaf(0.5f, tanh_a(0.5f * gi), 0.5f);  // sigmoid(gi)
            float tg = tanh_a(gg);
            float c  = si * tg;
            float tc = tanh_a(c);
            float so = fmaf(0.5f, tanh_a(0.5f * go), 0.5f);  // sigmoid(go)
            float hh = so * tc;

            y0 = fmaf(C.y, hh, y0);
            y1 = fmaf(C.z, hh, y1);
        }
        v[2 * lt]     = y0;
        v[2 * lt + 1] = y1;
    }

    float2* yp = reinterpret_cast<float2*>(y + m * FPT);
#pragma unroll
    for (int i = 0; i < LPT; i++) yp[i] = vp[i];
}

extern "C" void kernel_launch(void* const* d_in, const int* in_sizes, int n_in,
                              void* d_out, int out_size)
{
    const float* x   = (const float*)d_in[0];
    const float* Wih = (const float*)d_in[1];
    const float* bih = (const float*)d_in[2];
    const float* bhh = (const float*)d_in[3];
    const float* Wfc = (const float*)d_in[4];
    const float* bfc = (const float*)d_in[5];
    float* yd = (float*)d_out;

    int B = 131072;
    if (in_sizes && in_sizes[0] > 0) B = in_sizes[0] / (NT * 2);
    const int total = B * PARTS;
    lstm42_kernel<<<total / TPB, TPB>>>(x, Wih, bih, bhh, Wfc, bfc, yd);
}

// round 7
// speedup vs baseline: 2.0479x; 1.8214x over previous
#include <cuda_runtime.h>
#include <cstddef>

// PerLeadTimeLSTM: B=131072, LEADS=42, INPUT_DIM=2, HIDDEN=10
// Single timestep, zero init state => f gate dead.
// Layout: block = 224 threads (7 warps) x 64-row batch tile, STATIC smem.
//   warp w owns leads 6w..6w+5  -> weight smem loads are warp-uniform broadcasts
//   lane l owns rows l, l+32 (G=2) -> weights amortized 2x
//   x tile staged in smem with odd stride 85 -> conflict-free scalar access,
//   y computed in place over x slots, global I/O fully coalesced (float4).

#define TPB 224
#define NT 42
#define NH 10
#define RT 64            // batch rows per block tile
#define G 2              // rows per lane
#define LW 6             // leads per warp (7 warps * 6 = 42)

// Per-(lead,h) packed weights: 12 floats = 3 float4
//  A: [wi0, wi1, wg0, wg1]
//  B: [wo0, wo1, bias_i, bias_g]
//  C: [bias_o, wfc_d0, wfc_d1, pad]
#define HSTRIDE 12
#define WSTR (NH * HSTRIDE)      // 120 floats per lead
#define XSTR 85                  // odd stride -> conflict-free

__device__ __forceinline__ float tanh_a(float v) {
    float r; asm("tanh.approx.f32 %0, %1;" : "=f"(r) : "f"(v)); return r;
}

__global__ void __launch_bounds__(TPB)
lstm42_kernel(const float* __restrict__ x,
              const float* __restrict__ Wih,
              const float* __restrict__ bih,
              const float* __restrict__ bhh,
              const float* __restrict__ Wfc,
              const float* __restrict__ bfc,
              float* __restrict__ y)
{
    __shared__ __align__(16) float sw[NT * WSTR];   // 5040 floats
    __shared__ float sfc[NT * 2];                   // 84 floats
    __shared__ __align__(16) float sx[RT * XSTR];   // 5440 floats

    const int tid = threadIdx.x;

    // ---- Pack weights into shared ----
    for (int idx = tid; idx < NT * WSTR; idx += TPB) {
        int t = idx / WSTR;
        int r = idx - t * WSTR;
        int h = r / HSTRIDE;
        int k = r - h * HSTRIDE;
        float v = 0.f;
        // PyTorch gate row order: i=0..9, f=10..19, g=20..29, o=30..39
        if (k < 2)       v = Wih[t * 80 + h * 2 + k];                 // i
        else if (k < 4)  v = Wih[t * 80 + (20 + h) * 2 + (k - 2)];    // g
        else if (k < 6)  v = Wih[t * 80 + (30 + h) * 2 + (k - 4)];    // o
        else if (k == 6) v = bih[t * 40 + h]      + bhh[t * 40 + h];
        else if (k == 7) v = bih[t * 40 + 20 + h] + bhh[t * 40 + 20 + h];
        else if (k == 8) v = bih[t * 40 + 30 + h] + bhh[t * 40 + 30 + h];
        else if (k == 9)  v = Wfc[t * 20 + h];         // d=0 row
        else if (k == 10) v = Wfc[t * 20 + 10 + h];    // d=1 row
        sw[idx] = v;
    }
    for (int idx = tid; idx < NT * 2; idx += TPB) sfc[idx] = bfc[idx];

    // ---- Stage x tile: coalesced float4 global reads, remap stride 84->85 ----
    const size_t base = (size_t)blockIdx.x * (RT * 84);
    const float4* xg = reinterpret_cast<const float4*>(x + base);
#pragma unroll
    for (int it = 0; it < (RT * 84 / 4) / TPB; it++) {     // 6 iterations
        int i4 = it * TPB + tid;
        float4 vv = xg[i4];
        int f = i4 * 4;
        int r = f / 84;
        int c = f - r * 84;
        float* p = sx + r * XSTR + c;
        p[0] = vv.x; p[1] = vv.y; p[2] = vv.z; p[3] = vv.w;
    }
    __syncthreads();

    // ---- Compute: warp-uniform lead, G rows per lane ----
    const int wid  = tid >> 5;
    const int lane = tid & 31;

#pragma unroll 1
    for (int lt = 0; lt < LW; lt++) {
        const int t = wid * LW + lt;
        const float4* w4 = reinterpret_cast<const float4*>(sw + t * WSTR);
        const float bf0 = sfc[2 * t];
        const float bf1 = sfc[2 * t + 1];

        float x0[G], x1[G], y0[G], y1[G];
#pragma unroll
        for (int j = 0; j < G; j++) {
            float* p = sx + (lane + 32 * j) * XSTR + 2 * t;
            x0[j] = p[0];
            x1[j] = p[1];
            y0[j] = bf0;
            y1[j] = bf1;
        }

#pragma unroll
        for (int h = 0; h < NH; h++) {
            float4 A = w4[h * 3 + 0];
            float4 B = w4[h * 3 + 1];
            float4 C = w4[h * 3 + 2];
#pragma unroll
            for (int j = 0; j < G; j++) {
                float gi = fmaf(A.x, x0[j], fmaf(A.y, x1[j], B.z));
                float gg = fmaf(A.z, x0[j], fmaf(A.w, x1[j], B.w));
                float go = fmaf(B.x, x0[j], fmaf(B.y, x1[j], C.x));

                float si = fmaf(0.5f, tanh_a(0.5f * gi), 0.5f);  // sigmoid
                float tg = tanh_a(gg);
                float c  = si * tg;
                float tc = tanh_a(c);
                float so = fmaf(0.5f, tanh_a(0.5f * go), 0.5f);  // sigmoid
                float hh = so * tc;

                y0[j] = fmaf(C.y, hh, y0[j]);
                y1[j] = fmaf(C.z, hh, y1[j]);
            }
        }

#pragma unroll
        for (int j = 0; j < G; j++) {
            float* p = sx + (lane + 32 * j) * XSTR + 2 * t;
            p[0] = y0[j];
            p[1] = y1[j];
        }
    }
    __syncthreads();

    // ---- Stage out: remap 85->84, coalesced float4 global writes ----
    float4* yg = reinterpret_cast<float4*>(y + base);
#pragma unroll
    for (int it = 0; it < (RT * 84 / 4) / TPB; it++) {
        int i4 = it * TPB + tid;
        int f = i4 * 4;
        int r = f / 84;
        int c = f - r * 84;
        const float* p = sx + r * XSTR + c;
        float4 vv;
        vv.x = p[0]; vv.y = p[1]; vv.z = p[2]; vv.w = p[3];
        yg[i4] = vv;
    }
}

extern "C" void kernel_launch(void* const* d_in, const int* in_sizes, int n_in,
                              void* d_out, int out_size)
{
    const float* x   = (const float*)d_in[0];
    const float* Wih = (const float*)d_in[1];
    const float* bih = (const float*)d_in[2];
    const float* bhh = (const float*)d_in[3];
    const float* Wfc = (const float*)d_in[4];
    const float* bfc = (const float*)d_in[5];
    float* yd = (float*)d_out;

    int B = 131072;
    if (in_sizes && in_sizes[0] > 0) B = in_sizes[0] / (NT * 2);

    lstm42_kernel<<<B / RT, TPB>>>(x, Wih, bih, bhh, Wfc, bfc, yd);
}

// round 10
// speedup vs baseline: 2.0760x; 1.0137x over previous
#include <cuda_runtime.h>
#include <cstddef>

// PerLeadTimeLSTM: B=131072, LEADS=42, INPUT_DIM=2, HIDDEN=10
// Single timestep, zero init state => f gate dead.
// Layout: block = 224 threads (7 warps) x 64-row batch tile, STATIC smem.
//   warp w owns leads 6w..6w+5 -> weight smem loads warp-uniform broadcasts
//   lane l owns rows l, l+32 (G=2); leads processed in PAIRS -> 4 independent
//   activation chains per lane (latency cover) with no extra smem.
//   x tile stride 86 -> float2 access conflict-free (86/2=43 odd), y in place.

#define TPB 224
#define NT 42
#define NH 10
#define RT 64            // batch rows per block tile
#define G 2              // rows per lane
#define LW 6             // leads per warp (7 warps * 6 = 42)

// Per-(lead,h) packed weights: 12 floats = 3 float4
//  A: [wi0, wi1, wg0, wg1]
//  B: [wo0, wo1, bias_i, bias_g]
//  C: [bias_o, wfc_d0, wfc_d1, pad]
#define HSTRIDE 12
#define WSTR (NH * HSTRIDE)      // 120 floats per lead
#define XSTR 86                  // even stride; 43 odd -> float2 conflict-free

__device__ __forceinline__ float tanh_a(float v) {
    float r; asm("tanh.approx.f32 %0, %1;" : "=f"(r) : "f"(v)); return r;
}

__global__ void __launch_bounds__(TPB)
lstm42_kernel(const float* __restrict__ x,
              const float* __restrict__ Wih,
              const float* __restrict__ bih,
              const float* __restrict__ bhh,
              const float* __restrict__ Wfc,
              const float* __restrict__ bfc,
              float* __restrict__ y)
{
    __shared__ __align__(16) float sw[NT * WSTR];   // 5040 floats
    __shared__ float sfc[NT * 2];                   // 84 floats
    __shared__ __align__(16) float sx[RT * XSTR];   // 5504 floats  (42.5 KB total)

    const int tid = threadIdx.x;

    // ---- Pack weights into shared ----
    for (int idx = tid; idx < NT * WSTR; idx += TPB) {
        int t = idx / WSTR;
        int r = idx - t * WSTR;
        int h = r / HSTRIDE;
        int k = r - h * HSTRIDE;
        float v = 0.f;
        // PyTorch gate row order: i=0..9, f=10..19, g=20..29, o=30..39
        if (k < 2)       v = Wih[t * 80 + h * 2 + k];                 // i
        else if (k < 4)  v = Wih[t * 80 + (20 + h) * 2 + (k - 2)];    // g
        else if (k < 6)  v = Wih[t * 80 + (30 + h) * 2 + (k - 4)];    // o
        else if (k == 6) v = bih[t * 40 + h]      + bhh[t * 40 + h];
        else if (k == 7) v = bih[t * 40 + 20 + h] + bhh[t * 40 + 20 + h];
        else if (k == 8) v = bih[t * 40 + 30 + h] + bhh[t * 40 + 30 + h];
        else if (k == 9)  v = Wfc[t * 20 + h];         // d=0 row
        else if (k == 10) v = Wfc[t * 20 + 10 + h];    // d=1 row
        sw[idx] = v;
    }
    for (int idx = tid; idx < NT * 2; idx += TPB) sfc[idx] = bfc[idx];

    // ---- Stage x tile: coalesced float4 global reads, remap stride 84->86 ----
    const size_t base = (size_t)blockIdx.x * (RT * 84);
    const float4* xg = reinterpret_cast<const float4*>(x + base);
#pragma unroll
    for (int it = 0; it < (RT * 84 / 4) / TPB; it++) {     // 6 iterations
        int i4 = it * TPB + tid;
        float4 vv = xg[i4];
        int f = i4 * 4;
        int r = f / 84;
        int c = f - r * 84;
        float* p = sx + r * XSTR + c;
        p[0] = vv.x; p[1] = vv.y; p[2] = vv.z; p[3] = vv.w;
    }
    __syncthreads();

    // ---- Compute: warp-uniform leads in pairs, G rows per lane ----
    const int wid  = tid >> 5;
    const int lane = tid & 31;

#pragma unroll 1
    for (int lp = 0; lp < LW / 2; lp++) {
        const int t0 = wid * LW + 2 * lp;
        const int t1 = t0 + 1;
        const float4* wa = reinterpret_cast<const float4*>(sw + t0 * WSTR);
        const float4* wb = reinterpret_cast<const float4*>(sw + t1 * WSTR);
        const float af0 = sfc[2 * t0], af1 = sfc[2 * t0 + 1];
        const float bf0 = sfc[2 * t1], bf1 = sfc[2 * t1 + 1];

        float ax0[G], ax1[G], ay0[G], ay1[G];
        float bx0[G], bx1[G], by0[G], by1[G];
#pragma unroll
        for (int j = 0; j < G; j++) {
            const int row = (lane + 32 * j) * XSTR;
            const float2 xa = *reinterpret_cast<const float2*>(sx + row + 2 * t0);
            const float2 xb = *reinterpret_cast<const float2*>(sx + row + 2 * t1);
            ax0[j] = xa.x; ax1[j] = xa.y; ay0[j] = af0; ay1[j] = af1;
            bx0[j] = xb.x; bx1[j] = xb.y; by0[j] = bf0; by1[j] = bf1;
        }

#pragma unroll
        for (int h = 0; h < NH; h++) {
            float4 A0 = wa[h * 3 + 0], B0 = wa[h * 3 + 1], C0 = wa[h * 3 + 2];
            float4 A1 = wb[h * 3 + 0], B1 = wb[h * 3 + 1], C1 = wb[h * 3 + 2];
#pragma unroll
            for (int j = 0; j < G; j++) {
                // lead t0, row j
                float gi0 = fmaf(A0.x, ax0[j], fmaf(A0.y, ax1[j], B0.z));
                float gg0 = fmaf(A0.z, ax0[j], fmaf(A0.w, ax1[j], B0.w));
                float go0 = fmaf(B0.x, ax0[j], fmaf(B0.y, ax1[j], C0.x));
                // lead t1, row j
                float gi1 = fmaf(A1.x, bx0[j], fmaf(A1.y, bx1[j], B1.z));
                float gg1 = fmaf(A1.z, bx0[j], fmaf(A1.w, bx1[j], B1.w));
                float go1 = fmaf(B1.x, bx0[j], fmaf(B1.y, bx1[j], C1.x));

                float si0 = fmaf(0.5f, tanh_a(0.5f * gi0), 0.5f);
                float si1 = fmaf(0.5f, tanh_a(0.5f * gi1), 0.5f);
                float tg0 = tanh_a(gg0);
                float tg1 = tanh_a(gg1);
                float c0  = si0 * tg0;
                float c1  = si1 * tg1;
                float tc0 = tanh_a(c0);
                float tc1 = tanh_a(c1);
                float so0 = fmaf(0.5f, tanh_a(0.5f * go0), 0.5f);
                float so1 = fmaf(0.5f, tanh_a(0.5f * go1), 0.5f);
                float hh0 = so0 * tc0;
                float hh1 = so1 * tc1;

                ay0[j] = fmaf(C0.y, hh0, ay0[j]);
                ay1[j] = fmaf(C0.z, hh0, ay1[j]);
                by0[j] = fmaf(C1.y, hh1, by0[j]);
                by1[j] = fmaf(C1.z, hh1, by1[j]);
            }
        }

#pragma unroll
        for (int j = 0; j < G; j++) {
            const int row = (lane + 32 * j) * XSTR;
            float2 ya; ya.x = ay0[j]; ya.y = ay1[j];
            float2 yb; yb.x = by0[j]; yb.y = by1[j];
            *reinterpret_cast<float2*>(sx + row + 2 * t0) = ya;
            *reinterpret_cast<float2*>(sx + row + 2 * t1) = yb;
        }
    }
    __syncthreads();

    // ---- Stage out: remap 86->84, coalesced float4 global writes ----
    float4* yg = reinterpret_cast<float4*>(y + base);
#pragma unroll
    for (int it = 0; it < (RT * 84 / 4) / TPB; it++) {
        int i4 = it * TPB + tid;
        int f = i4 * 4;
        int r = f / 84;
        int c = f - r * 84;
        const float* p = sx + r * XSTR + c;
        float4 vv;
        vv.x = p[0]; vv.y = p[1]; vv.z = p[2]; vv.w = p[3];
        yg[i4] = vv;
    }
}

extern "C" void kernel_launch(void* const* d_in, const int* in_sizes, int n_in,
                              void* d_out, int out_size)
{
    const float* x   = (const float*)d_in[0];
    const float* Wih = (const float*)d_in[1];
    const float* bih = (const float*)d_in[2];
    const float* bhh = (const float*)d_in[3];
    const float* Wfc = (const float*)d_in[4];
    const float* bfc = (const float*)d_in[5];
    float* yd = (float*)d_out;

    int B = 131072;
    if (in_sizes && in_sizes[0] > 0) B = in_sizes[0] / (NT * 2);

    lstm42_kernel<<<B / RT, TPB>>>(x, Wih, bih, bhh, Wfc, bfc, yd);
}